// round 9
// baseline (speedup 1.0000x reference)
#include <cuda_runtime.h>
#include <cuda_pipeline.h>
#include <mma.h>
#include <cstdint>

using namespace nvcuda;

#define B_    8192
#define HID_  1024
#define H_    64
#define Q_    99
#define NTOT  704   // 64 (median) + 640 (inc)

// Scratch for GEMM output (allocation-free rule: __device__ global)
__device__ float g_y[B_ * NTOT];

// ---------------------------------------------------------------------------
// GEMM: y[B, 704] = x[B,1024] @ [Wm(1024x64) | Wi(1024x640)]   (TF32 WMMA)
// Block tile: 128(M) x 64(N) x 32(K), 8 warps (4x2), each warp 32x32.
// 2-stage cp.async pipeline; constant wait_group via always-commit protocol.
// Tile buffers live in DYNAMIC shared memory (59,392 B > 48 KB static cap).
// ---------------------------------------------------------------------------
#define BM 128
#define BN 64
#define BK 32

// Dynamic smem layout: As[2][BM][BK+8] then Bs[2][BK][BN+8]
#define AS_STRIDE (BK + 8)                      // 40 floats = 160 B (16B mult)
#define BS_STRIDE (BN + 8)                      // 72 floats = 288 B (16B mult)
#define AS_ELEMS  (2 * BM * AS_STRIDE)          // 10240 floats
#define BS_ELEMS  (2 * BK * BS_STRIDE)          // 4608 floats
#define GEMM_SMEM_BYTES ((AS_ELEMS + BS_ELEMS) * 4)   // 59392 B

__global__ __launch_bounds__(256) void hqp_gemm(const float* __restrict__ x,
                                                const float* __restrict__ Wm,
                                                const float* __restrict__ Wi)
{
    extern __shared__ float smem_dyn[];
    typedef float AsTile[BM][AS_STRIDE];
    typedef float BsTile[BK][BS_STRIDE];
    AsTile* As = reinterpret_cast<AsTile*>(smem_dyn);             // As[2]
    BsTile* Bs = reinterpret_cast<BsTile*>(smem_dyn + AS_ELEMS);  // Bs[2]

    const int tid  = threadIdx.x;
    const int warp = tid >> 5;
    const int wm   = warp & 3;   // 0..3  -> 32 rows each
    const int wn   = warp >> 2;  // 0..1  -> 32 cols each
    const int m0   = blockIdx.y * BM;

    // N-tile 0 comes from Wm (ld 64); tiles 1..10 from Wi (ld 640)
    const float* W;
    int ldw, ncol;
    if (blockIdx.x == 0) { W = Wm; ldw = 64;  ncol = 0; }
    else                 { W = Wi; ldw = 640; ncol = (blockIdx.x - 1) * 64; }

    // Per-thread load coordinates (fixed across iterations)
    const int ar[4] = { (tid + 0) >> 3, (tid + 256) >> 3, (tid + 512) >> 3, (tid + 768) >> 3 };
    const int ac    = (tid & 7) * 4;
    const int br[2] = { (tid + 0) >> 4, (tid + 256) >> 4 };
    const int bc    = (tid & 15) * 4;

    auto load_tiles = [&](int kt, int s) {
        #pragma unroll
        for (int t = 0; t < 4; t++)
            __pipeline_memcpy_async(&As[s][ar[t]][ac],
                                    &x[(size_t)(m0 + ar[t]) * HID_ + kt + ac], 16);
        #pragma unroll
        for (int t = 0; t < 2; t++)
            __pipeline_memcpy_async(&Bs[s][br[t]][bc],
                                    &W[(size_t)(kt + br[t]) * ldw + ncol + bc], 16);
    };

    wmma::fragment<wmma::accumulator, 16, 16, 8, float> c[2][2];
    #pragma unroll
    for (int i = 0; i < 2; i++)
        #pragma unroll
        for (int j = 0; j < 2; j++)
            wmma::fill_fragment(c[i][j], 0.0f);

    // Prologue: stage 0 in flight (group G0)
    load_tiles(0, 0);
    __pipeline_commit();

    for (int kt = 0; kt < HID_; kt += BK) {
        const int s = (kt >> 5) & 1;
        if (kt + BK < HID_)
            load_tiles(kt + BK, s ^ 1);   // prev-iter bottom sync protects s^1
        __pipeline_commit();              // ALWAYS commit (last iter: empty group)
        __pipeline_wait_prior(1);         // constant immediate: stage s resident
        __syncthreads();

        #pragma unroll
        for (int ks = 0; ks < BK; ks += 8) {
            wmma::fragment<wmma::matrix_a, 16, 16, 8, wmma::precision::tf32, wmma::row_major> a[2];
            wmma::fragment<wmma::matrix_b, 16, 16, 8, wmma::precision::tf32, wmma::row_major> b[2];
            #pragma unroll
            for (int i = 0; i < 2; i++) {
                wmma::load_matrix_sync(a[i], &As[s][wm * 32 + i * 16][ks], AS_STRIDE);
                #pragma unroll
                for (int e = 0; e < a[i].num_elements; e++)
                    a[i].x[e] = wmma::__float_to_tf32(a[i].x[e]);
            }
            #pragma unroll
            for (int j = 0; j < 2; j++) {
                wmma::load_matrix_sync(b[j], &Bs[s][ks][wn * 32 + j * 16], BS_STRIDE);
                #pragma unroll
                for (int e = 0; e < b[j].num_elements; e++)
                    b[j].x[e] = wmma::__float_to_tf32(b[j].x[e]);
            }
            #pragma unroll
            for (int i = 0; i < 2; i++)
                #pragma unroll
                for (int j = 0; j < 2; j++)
                    wmma::mma_sync(c[i][j], a[i], b[j], c[i][j]);
        }
        __syncthreads();
    }

    const int col0 = (blockIdx.x == 0) ? 0 : 64 + (blockIdx.x - 1) * 64;
    #pragma unroll
    for (int i = 0; i < 2; i++)
        #pragma unroll
        for (int j = 0; j < 2; j++) {
            int row = m0 + wm * 32 + i * 16;
            int col = col0 + wn * 32 + j * 16;
            wmma::store_matrix_sync(&g_y[(size_t)row * NTOT + col], c[i][j], NTOT, wmma::mem_row_major);
        }
}

// ---------------------------------------------------------------------------
// Epilogue: one block per batch row b (256 threads).  Static smem ~7.7 KB.
//  - rank[p] = stable-argsort rank of quantiles[b,p]
//  - m = rank of element minimizing |q-0.5| (first-in-sorted tie break)
//  - inc[h][0..9] = softplus(yI + bi); cum0[s] = (s/10)*S10[h] + pre[h][s%10]
//  - out[b,h,p] = fma(sa[p], S10[h], fma(sgn[p], pre[h][rr[p]], med[h]))
// g_y reads via __ldcs (read-once scratch); output via __stcs (write-once).
// ---------------------------------------------------------------------------
__global__ __launch_bounds__(256) void hqp_epilogue(const float* __restrict__ quant,
                                                    const float* __restrict__ bm,
                                                    const float* __restrict__ bi,
                                                    float* __restrict__ out)
{
    __shared__ float qs[Q_];
    __shared__ int   rk[Q_];
    __shared__ float sgnv[Q_];
    __shared__ float sav[Q_];      // sgn * (steps/10), pre-scaled for FMA
    __shared__ int   rrv[Q_];
    __shared__ float med[H_];
    __shared__ float inc[H_ * 10];
    __shared__ float pre[H_][10];
    __shared__ float S10[H_];
    __shared__ unsigned long long mpack;

    const int b   = blockIdx.x;
    const int tid = threadIdx.x;

    if (tid == 0) mpack = ~0ULL;
    if (tid < Q_) qs[tid] = quant[(size_t)b * Q_ + tid];

    const float* yrow = &g_y[(size_t)b * NTOT];

    // softplus(z) = max(z,0) + log1p(exp(-|z|))   (JAX logaddexp(z, 0))
    // yrow is 16B-aligned (NTOT*4 = 2816 B row stride); offset 64 floats = 256 B.
    {
        const float4* y4  = reinterpret_cast<const float4*>(yrow + 64);
        const float4* bi4 = reinterpret_cast<const float4*>(bi);
        for (int v = tid; v < (H_ * 10) / 4; v += 256) {
            float4 yv = __ldcs(&y4[v]);    // read-once scratch: evict-first
            float4 bv = bi4[v];
            #pragma unroll
            for (int e = 0; e < 4; e++) {
                float z = ((const float*)&yv)[e] + ((const float*)&bv)[e];
                inc[v * 4 + e] = fmaxf(z, 0.0f) + log1pf(expf(-fabsf(z)));
            }
        }
    }
    if (tid < H_) med[tid] = __ldcs(&yrow[tid]) + bm[tid];
    __syncthreads();

    if (tid < Q_) {
        float q = qs[tid];
        int r = 0;
        for (int j = 0; j < Q_; j++) {
            float qj = qs[j];
            r += (qj < q) || (qj == q && j < tid);   // stable argsort rank
        }
        rk[tid] = r;
        // argmin over sorted |q-0.5|, first occurrence -> lexicographic (key, rank)
        unsigned int kb = __float_as_uint(fabsf(q - 0.5f));   // nonneg: bit-monotonic
        unsigned long long cand = ((unsigned long long)kb << 32) | (unsigned)r;
        atomicMin(&mpack, cand);
    }
    if (tid < H_) {
        float s = 0.0f;
        #pragma unroll
        for (int j = 0; j < 10; j++) { pre[tid][j] = s; s += inc[tid * 10 + j]; }
        S10[tid] = s;
    }
    __syncthreads();

    // Hoist per-p terms; pre-scale so the output loop is exactly 2 FMAs.
    const int m = (int)(mpack & 0xffffffffu);
    if (tid < Q_) {
        int d = rk[tid] - m;
        int s = d < 0 ? -d : d;
        float sg = (d > 0) ? 1.0f : (d < 0 ? -1.0f : 0.0f);
        int a = s / 10;
        sgnv[tid] = sg;
        sav[tid]  = sg * (float)a;
        rrv[tid]  = s - a * 10;
    }
    __syncthreads();

    // Vectorized output: 6336 floats = 1584 float4 (row base 6336*4 B: 16B-aligned).
    // Streaming (.cs) stores: output is write-once; don't evict useful L2 lines.
    float4* orow4 = reinterpret_cast<float4*>(out + (size_t)b * (H_ * Q_));
    for (int v = tid; v < (H_ * Q_) / 4; v += 256) {
        int base = v * 4;
        float4 o;
        #pragma unroll
        for (int e = 0; e < 4; e++) {
            int idx = base + e;
            int h = idx / Q_;
            int p = idx - h * Q_;
            ((float*)&o)[e] = fmaf(sav[p], S10[h],
                                   fmaf(sgnv[p], pre[h][rrv[p]], med[h]));
        }
        __stcs(&orow4[v], o);
    }
}

// ---------------------------------------------------------------------------
// Inputs mapped by ELEMENT COUNT (robust to metadata ordering):
//   x: 8388608, quantiles: 811008, Wm: 65536, bm: 64, Wi: 655360, bi: 640
// Output: (B, 64, 99) f32
// ---------------------------------------------------------------------------
extern "C" void kernel_launch(void* const* d_in, const int* in_sizes, int n_in,
                              void* d_out, int out_size)
{
    const float *x = nullptr, *qu = nullptr, *Wm = nullptr,
                *bm = nullptr, *Wi = nullptr, *bi = nullptr;
    for (int i = 0; i < n_in; i++) {
        switch (in_sizes[i]) {
            case B_ * HID_:      x  = (const float*)d_in[i]; break;  // 8388608
            case B_ * Q_:        qu = (const float*)d_in[i]; break;  // 811008
            case HID_ * H_:      Wm = (const float*)d_in[i]; break;  // 65536
            case H_:             bm = (const float*)d_in[i]; break;  // 64
            case HID_ * H_ * 10: Wi = (const float*)d_in[i]; break;  // 655360
            case H_ * 10:        bi = (const float*)d_in[i]; break;  // 640
            default: break;
        }
    }
    float* out = (float*)d_out;

    // Opt in to >48KB dynamic shared memory for the GEMM. Attribute setter:
    // not a stream op / allocation; legal during capture; idempotent.
    cudaFuncSetAttribute(hqp_gemm, cudaFuncAttributeMaxDynamicSharedMemorySize,
                         GEMM_SMEM_BYTES);

    dim3 ggrid(NTOT / BN, B_ / BM);   // 11 x 64
    hqp_gemm<<<ggrid, 256, GEMM_SMEM_BYTES>>>(x, Wm, Wi);
    hqp_epilogue<<<B_, 256>>>(qu, bm, bi, out);
}

// round 13
// speedup vs baseline: 1.1826x; 1.1826x over previous
#include <cuda_runtime.h>
#include <cuda_pipeline.h>
#include <mma.h>
#include <cstdint>

using namespace nvcuda;

#define B_    8192
#define HID_  1024
#define H_    64
#define Q_    99
#define NTOT  704   // 64 (median) + 640 (inc)

// Scratch for GEMM output (allocation-free rule: __device__ global)
__device__ float g_y[B_ * NTOT];

// ---------------------------------------------------------------------------
// GEMM: y[B, 704] = x[B,1024] @ [Wm(1024x64) | Wi(1024x640)]   (TF32 WMMA)
// Block tile: 128(M) x 64(N) x 32(K), 8 warps (4x2), each warp 32x32.
// 2-stage cp.async pipeline; constant wait_group via always-commit protocol.
// Dynamic shared memory (59,392 B). tf32 conversion loops removed: HMMA.TF32
// truncates operand mantissas in HW; error budget (1e-3) absorbs it.
// ---------------------------------------------------------------------------
#define BM 128
#define BN 64
#define BK 32

#define AS_STRIDE (BK + 8)                      // 40 floats = 160 B (16B mult)
#define BS_STRIDE (BN + 8)                      // 72 floats = 288 B (16B mult)
#define AS_ELEMS  (2 * BM * AS_STRIDE)          // 10240 floats
#define BS_ELEMS  (2 * BK * BS_STRIDE)          // 4608 floats
#define GEMM_SMEM_BYTES ((AS_ELEMS + BS_ELEMS) * 4)   // 59392 B

__global__ __launch_bounds__(256) void hqp_gemm(const float* __restrict__ x,
                                                const float* __restrict__ Wm,
                                                const float* __restrict__ Wi)
{
    extern __shared__ float smem_dyn[];
    typedef float AsTile[BM][AS_STRIDE];
    typedef float BsTile[BK][BS_STRIDE];
    AsTile* As = reinterpret_cast<AsTile*>(smem_dyn);             // As[2]
    BsTile* Bs = reinterpret_cast<BsTile*>(smem_dyn + AS_ELEMS);  // Bs[2]

    const int tid  = threadIdx.x;
    const int warp = tid >> 5;
    const int wm   = warp & 3;   // 0..3  -> 32 rows each
    const int wn   = warp >> 2;  // 0..1  -> 32 cols each
    const int m0   = blockIdx.y * BM;

    // N-tile 0 comes from Wm (ld 64); tiles 1..10 from Wi (ld 640)
    const float* W;
    int ldw, ncol;
    if (blockIdx.x == 0) { W = Wm; ldw = 64;  ncol = 0; }
    else                 { W = Wi; ldw = 640; ncol = (blockIdx.x - 1) * 64; }

    // Per-thread load coordinates (fixed across iterations)
    const int ar[4] = { (tid + 0) >> 3, (tid + 256) >> 3, (tid + 512) >> 3, (tid + 768) >> 3 };
    const int ac    = (tid & 7) * 4;
    const int br[2] = { (tid + 0) >> 4, (tid + 256) >> 4 };
    const int bc    = (tid & 15) * 4;

    auto load_tiles = [&](int kt, int s) {
        #pragma unroll
        for (int t = 0; t < 4; t++)
            __pipeline_memcpy_async(&As[s][ar[t]][ac],
                                    &x[(size_t)(m0 + ar[t]) * HID_ + kt + ac], 16);
        #pragma unroll
        for (int t = 0; t < 2; t++)
            __pipeline_memcpy_async(&Bs[s][br[t]][bc],
                                    &W[(size_t)(kt + br[t]) * ldw + ncol + bc], 16);
    };

    wmma::fragment<wmma::accumulator, 16, 16, 8, float> c[2][2];
    #pragma unroll
    for (int i = 0; i < 2; i++)
        #pragma unroll
        for (int j = 0; j < 2; j++)
            wmma::fill_fragment(c[i][j], 0.0f);

    // Prologue: stage 0 in flight (group G0)
    load_tiles(0, 0);
    __pipeline_commit();

    for (int kt = 0; kt < HID_; kt += BK) {
        const int s = (kt >> 5) & 1;
        if (kt + BK < HID_)
            load_tiles(kt + BK, s ^ 1);   // prev-iter bottom sync protects s^1
        __pipeline_commit();              // ALWAYS commit (last iter: empty group)
        __pipeline_wait_prior(1);         // constant immediate: stage s resident
        __syncthreads();

        #pragma unroll
        for (int ks = 0; ks < BK; ks += 8) {
            wmma::fragment<wmma::matrix_a, 16, 16, 8, wmma::precision::tf32, wmma::row_major> a[2];
            wmma::fragment<wmma::matrix_b, 16, 16, 8, wmma::precision::tf32, wmma::row_major> b[2];
            #pragma unroll
            for (int i = 0; i < 2; i++)
                wmma::load_matrix_sync(a[i], &As[s][wm * 32 + i * 16][ks], AS_STRIDE);
            #pragma unroll
            for (int j = 0; j < 2; j++)
                wmma::load_matrix_sync(b[j], &Bs[s][ks][wn * 32 + j * 16], BS_STRIDE);
            // No explicit __float_to_tf32: HW truncation is within error budget.
            #pragma unroll
            for (int i = 0; i < 2; i++)
                #pragma unroll
                for (int j = 0; j < 2; j++)
                    wmma::mma_sync(c[i][j], a[i], b[j], c[i][j]);
        }
        __syncthreads();
    }

    const int col0 = (blockIdx.x == 0) ? 0 : 64 + (blockIdx.x - 1) * 64;
    #pragma unroll
    for (int i = 0; i < 2; i++)
        #pragma unroll
        for (int j = 0; j < 2; j++) {
            int row = m0 + wm * 32 + i * 16;
            int col = col0 + wn * 32 + j * 16;
            wmma::store_matrix_sync(&g_y[(size_t)row * NTOT + col], c[i][j], NTOT, wmma::mem_row_major);
        }
}

// ---------------------------------------------------------------------------
// Epilogue: one block per batch row b (256 threads).
// Output loop inverted: thread owns p (regs: sg, sa, rr), loops h.
//  - S10[h]/med[h]: warp-uniform LDS (broadcast, conflict-free)
//  - pre[h][rr]: 10 consecutive words -> <=10 banks, broadcast dups -> N~1
//  - no div-by-99 in the hot loop; stores coalesced STG.32 over p
// ---------------------------------------------------------------------------
__global__ __launch_bounds__(256) void hqp_epilogue(const float* __restrict__ quant,
                                                    const float* __restrict__ bm,
                                                    const float* __restrict__ bi,
                                                    float* __restrict__ out)
{
    __shared__ float qs[Q_];
    __shared__ float sgnv[Q_];
    __shared__ float sav[Q_];      // sgn * (steps/10), pre-scaled for FMA
    __shared__ int   rrv[Q_];
    __shared__ float med[H_];
    __shared__ float inc[H_ * 10];
    __shared__ float pre[H_][10];
    __shared__ float S10[H_];
    __shared__ unsigned long long mpack;

    const int b   = blockIdx.x;
    const int tid = threadIdx.x;

    if (tid == 0) mpack = ~0ULL;
    if (tid < Q_) qs[tid] = quant[(size_t)b * Q_ + tid];

    const float* yrow = &g_y[(size_t)b * NTOT];

    // softplus(z) = max(z,0) + log1p(exp(-|z|))   (JAX logaddexp(z, 0))
    {
        const float4* y4  = reinterpret_cast<const float4*>(yrow + 64);
        const float4* bi4 = reinterpret_cast<const float4*>(bi);
        for (int v = tid; v < (H_ * 10) / 4; v += 256) {
            float4 yv = __ldcs(&y4[v]);    // read-once scratch: evict-first
            float4 bv = bi4[v];
            #pragma unroll
            for (int e = 0; e < 4; e++) {
                float z = ((const float*)&yv)[e] + ((const float*)&bv)[e];
                inc[v * 4 + e] = fmaxf(z, 0.0f) + log1pf(expf(-fabsf(z)));
            }
        }
    }
    if (tid < H_) med[tid] = __ldcs(&yrow[tid]) + bm[tid];
    __syncthreads();

    if (tid < Q_) {
        float q = qs[tid];
        int r = 0;
        for (int j = 0; j < Q_; j++) {
            float qj = qs[j];
            r += (qj < q) || (qj == q && j < tid);   // stable argsort rank
        }
        // argmin over sorted |q-0.5|, first occurrence -> lexicographic (key, rank)
        unsigned int kb = __float_as_uint(fabsf(q - 0.5f));   // nonneg: bit-monotonic
        unsigned long long cand = ((unsigned long long)kb << 32) | (unsigned)r;
        atomicMin(&mpack, cand);
        sgnv[tid] = __int_as_float(r);     // temp: park rank bits for next pass
    }
    if (tid < H_) {
        float s = 0.0f;
        #pragma unroll
        for (int j = 0; j < 10; j++) { pre[tid][j] = s; s += inc[tid * 10 + j]; }
        S10[tid] = s;
    }
    __syncthreads();

    // Per-p terms: exactly the 2-FMA coefficients for the hot loop.
    const int m = (int)(mpack & 0xffffffffu);
    if (tid < Q_) {
        int r = __float_as_int(sgnv[tid]);
        int d = r - m;
        int s = d < 0 ? -d : d;
        float sg = (d > 0) ? 1.0f : (d < 0 ? -1.0f : 0.0f);
        int a = s / 10;
        sgnv[tid] = sg;
        sav[tid]  = sg * (float)a;
        rrv[tid]  = s - a * 10;
    }
    __syncthreads();

    // Hot loop: thread owns p (lane 0..98 of each 128-half), iterates h.
    // sub selects even/odd h so both halves of the block stay busy.
    const int p   = tid & 127;
    const int sub = tid >> 7;          // 0 or 1
    if (p < Q_) {
        const float sg = sgnv[p];
        const float sa = sav[p];
        const int   rr = rrv[p];
        float* orow = out + (size_t)b * (H_ * Q_) + p;
        #pragma unroll 4
        for (int hh = 0; hh < H_ / 2; hh++) {
            const int h = hh * 2 + sub;
            float o = fmaf(sa, S10[h], fmaf(sg, pre[h][rr], med[h]));
            __stcs(&orow[h * Q_], o);
        }
    }
}

// ---------------------------------------------------------------------------
// Inputs mapped by ELEMENT COUNT (robust to metadata ordering):
//   x: 8388608, quantiles: 811008, Wm: 65536, bm: 64, Wi: 655360, bi: 640
// Output: (B, 64, 99) f32
// ---------------------------------------------------------------------------
extern "C" void kernel_launch(void* const* d_in, const int* in_sizes, int n_in,
                              void* d_out, int out_size)
{
    const float *x = nullptr, *qu = nullptr, *Wm = nullptr,
                *bm = nullptr, *Wi = nullptr, *bi = nullptr;
    for (int i = 0; i < n_in; i++) {
        switch (in_sizes[i]) {
            case B_ * HID_:      x  = (const float*)d_in[i]; break;  // 8388608
            case B_ * Q_:        qu = (const float*)d_in[i]; break;  // 811008
            case HID_ * H_:      Wm = (const float*)d_in[i]; break;  // 65536
            case H_:             bm = (const float*)d_in[i]; break;  // 64
            case HID_ * H_ * 10: Wi = (const float*)d_in[i]; break;  // 655360
            case H_ * 10:        bi = (const float*)d_in[i]; break;  // 640
            default: break;
        }
    }
    float* out = (float*)d_out;

    cudaFuncSetAttribute(hqp_gemm, cudaFuncAttributeMaxDynamicSharedMemorySize,
                         GEMM_SMEM_BYTES);

    dim3 ggrid(NTOT / BN, B_ / BM);   // 11 x 64
    hqp_gemm<<<ggrid, 256, GEMM_SMEM_BYTES>>>(x, Wm, Wi);
    hqp_epilogue<<<B_, 256>>>(qu, bm, bi, out);
}

// round 15
// speedup vs baseline: 1.2316x; 1.0414x over previous
#include <cuda_runtime.h>
#include <cuda_pipeline.h>
#include <mma.h>
#include <cstdint>

using namespace nvcuda;

#define B_    8192
#define HID_  1024
#define H_    64
#define Q_    99
#define NTOT  704   // 64 (median) + 640 (inc)

// Scratch for GEMM output (allocation-free rule: __device__ global)
__device__ float g_y[B_ * NTOT];

// ---------------------------------------------------------------------------
// GEMM: y[B, 704] = x[B,1024] @ [Wm(1024x64) | Wi(1024x640)]   (TF32 WMMA)
// Block tile: 128(M) x 64(N) x 32(K), 4 warps (2x2), warp tile 64x32.
// Rationale: tf32 load_matrix_sync = scalar LDS; 64x32 warp tile amortizes
// 6 fragment-loads over 8 MMAs per ks-step (vs 4:4 at 32x32) — issue-bound fix.
// 2-stage cp.async pipeline; constant wait_group via always-commit protocol.
// ---------------------------------------------------------------------------
#define BM 128
#define BN 64
#define BK 32

#define AS_STRIDE (BK + 8)                      // 40 floats = 160 B (16B mult)
#define BS_STRIDE (BN + 8)                      // 72 floats = 288 B (16B mult)
#define AS_ELEMS  (2 * BM * AS_STRIDE)          // 10240 floats
#define BS_ELEMS  (2 * BK * BS_STRIDE)          // 4608 floats
#define GEMM_SMEM_BYTES ((AS_ELEMS + BS_ELEMS) * 4)   // 59392 B

__global__ __launch_bounds__(128) void hqp_gemm(const float* __restrict__ x,
                                                const float* __restrict__ Wm,
                                                const float* __restrict__ Wi)
{
    extern __shared__ float smem_dyn[];
    typedef float AsTile[BM][AS_STRIDE];
    typedef float BsTile[BK][BS_STRIDE];
    AsTile* As = reinterpret_cast<AsTile*>(smem_dyn);             // As[2]
    BsTile* Bs = reinterpret_cast<BsTile*>(smem_dyn + AS_ELEMS);  // Bs[2]

    const int tid  = threadIdx.x;
    const int warp = tid >> 5;     // 0..3
    const int wm   = warp >> 1;    // 0..1 -> 64 rows each
    const int wn   = warp & 1;     // 0..1 -> 32 cols each
    const int m0   = blockIdx.y * BM;

    // N-tile 0 comes from Wm (ld 64); tiles 1..10 from Wi (ld 640)
    const float* W;
    int ldw, ncol;
    if (blockIdx.x == 0) { W = Wm; ldw = 64;  ncol = 0; }
    else                 { W = Wi; ldw = 640; ncol = (blockIdx.x - 1) * 64; }

    // Per-thread load coordinates (128 threads): A = 8 float4, B = 4 float4
    int ar[8], br[4];
    #pragma unroll
    for (int t = 0; t < 8; t++) ar[t] = (tid + t * 128) >> 3;
    #pragma unroll
    for (int t = 0; t < 4; t++) br[t] = (tid + t * 128) >> 4;
    const int ac = (tid & 7) * 4;
    const int bc = (tid & 15) * 4;

    auto load_tiles = [&](int kt, int s) {
        #pragma unroll
        for (int t = 0; t < 8; t++)
            __pipeline_memcpy_async(&As[s][ar[t]][ac],
                                    &x[(size_t)(m0 + ar[t]) * HID_ + kt + ac], 16);
        #pragma unroll
        for (int t = 0; t < 4; t++)
            __pipeline_memcpy_async(&Bs[s][br[t]][bc],
                                    &W[(size_t)(kt + br[t]) * ldw + ncol + bc], 16);
    };

    wmma::fragment<wmma::accumulator, 16, 16, 8, float> c[4][2];
    #pragma unroll
    for (int i = 0; i < 4; i++)
        #pragma unroll
        for (int j = 0; j < 2; j++)
            wmma::fill_fragment(c[i][j], 0.0f);

    // Prologue: stage 0 in flight (group G0)
    load_tiles(0, 0);
    __pipeline_commit();

    for (int kt = 0; kt < HID_; kt += BK) {
        const int s = (kt >> 5) & 1;
        if (kt + BK < HID_)
            load_tiles(kt + BK, s ^ 1);   // prev-iter bottom sync protects s^1
        __pipeline_commit();              // ALWAYS commit (last iter: empty group)
        __pipeline_wait_prior(1);         // constant immediate: stage s resident
        __syncthreads();

        #pragma unroll
        for (int ks = 0; ks < BK; ks += 8) {
            wmma::fragment<wmma::matrix_a, 16, 16, 8, wmma::precision::tf32, wmma::row_major> a[4];
            wmma::fragment<wmma::matrix_b, 16, 16, 8, wmma::precision::tf32, wmma::row_major> b[2];
            #pragma unroll
            for (int i = 0; i < 4; i++)
                wmma::load_matrix_sync(a[i], &As[s][wm * 64 + i * 16][ks], AS_STRIDE);
            #pragma unroll
            for (int j = 0; j < 2; j++)
                wmma::load_matrix_sync(b[j], &Bs[s][ks][wn * 32 + j * 16], BS_STRIDE);
            // No explicit __float_to_tf32: HW truncation within error budget (meas 1.45e-4).
            #pragma unroll
            for (int i = 0; i < 4; i++)
                #pragma unroll
                for (int j = 0; j < 2; j++)
                    wmma::mma_sync(c[i][j], a[i], b[j], c[i][j]);
        }
        __syncthreads();
    }

    const int col0 = (blockIdx.x == 0) ? 0 : 64 + (blockIdx.x - 1) * 64;
    #pragma unroll
    for (int i = 0; i < 4; i++)
        #pragma unroll
        for (int j = 0; j < 2; j++) {
            int row = m0 + wm * 64 + i * 16;
            int col = col0 + wn * 32 + j * 16;
            wmma::store_matrix_sync(&g_y[(size_t)row * NTOT + col], c[i][j], NTOT, wmma::mem_row_major);
        }
}

// ---------------------------------------------------------------------------
// Epilogue: one block per batch row b (256 threads). (Unchanged from R13 meas:
// 64.7us, alu-bound; next target after GEMM.)
// ---------------------------------------------------------------------------
__global__ __launch_bounds__(256) void hqp_epilogue(const float* __restrict__ quant,
                                                    const float* __restrict__ bm,
                                                    const float* __restrict__ bi,
                                                    float* __restrict__ out)
{
    __shared__ float qs[Q_];
    __shared__ float sgnv[Q_];
    __shared__ float sav[Q_];      // sgn * (steps/10), pre-scaled for FMA
    __shared__ int   rrv[Q_];
    __shared__ float med[H_];
    __shared__ float inc[H_ * 10];
    __shared__ float pre[H_][10];
    __shared__ float S10[H_];
    __shared__ unsigned long long mpack;

    const int b   = blockIdx.x;
    const int tid = threadIdx.x;

    if (tid == 0) mpack = ~0ULL;
    if (tid < Q_) qs[tid] = quant[(size_t)b * Q_ + tid];

    const float* yrow = &g_y[(size_t)b * NTOT];

    // softplus(z) = max(z,0) + log1p(exp(-|z|))   (JAX logaddexp(z, 0))
    {
        const float4* y4  = reinterpret_cast<const float4*>(yrow + 64);
        const float4* bi4 = reinterpret_cast<const float4*>(bi);
        for (int v = tid; v < (H_ * 10) / 4; v += 256) {
            float4 yv = __ldcs(&y4[v]);    // read-once scratch: evict-first
            float4 bv = bi4[v];
            #pragma unroll
            for (int e = 0; e < 4; e++) {
                float z = ((const float*)&yv)[e] + ((const float*)&bv)[e];
                inc[v * 4 + e] = fmaxf(z, 0.0f) + log1pf(expf(-fabsf(z)));
            }
        }
    }
    if (tid < H_) med[tid] = __ldcs(&yrow[tid]) + bm[tid];
    __syncthreads();

    if (tid < Q_) {
        float q = qs[tid];
        int r = 0;
        for (int j = 0; j < Q_; j++) {
            float qj = qs[j];
            r += (qj < q) || (qj == q && j < tid);   // stable argsort rank
        }
        // argmin over sorted |q-0.5|, first occurrence -> lexicographic (key, rank)
        unsigned int kb = __float_as_uint(fabsf(q - 0.5f));   // nonneg: bit-monotonic
        unsigned long long cand = ((unsigned long long)kb << 32) | (unsigned)r;
        atomicMin(&mpack, cand);
        sgnv[tid] = __int_as_float(r);     // temp: park rank bits for next pass
    }
    if (tid < H_) {
        float s = 0.0f;
        #pragma unroll
        for (int j = 0; j < 10; j++) { pre[tid][j] = s; s += inc[tid * 10 + j]; }
        S10[tid] = s;
    }
    __syncthreads();

    // Per-p terms: exactly the 2-FMA coefficients for the hot loop.
    const int m = (int)(mpack & 0xffffffffu);
    if (tid < Q_) {
        int r = __float_as_int(sgnv[tid]);
        int d = r - m;
        int s = d < 0 ? -d : d;
        float sg = (d > 0) ? 1.0f : (d < 0 ? -1.0f : 0.0f);
        int a = s / 10;
        sgnv[tid] = sg;
        sav[tid]  = sg * (float)a;
        rrv[tid]  = s - a * 10;
    }
    __syncthreads();

    // Hot loop: thread owns p (lane 0..98 of each 128-half), iterates h.
    const int p   = tid & 127;
    const int sub = tid >> 7;          // 0 or 1
    if (p < Q_) {
        const float sg = sgnv[p];
        const float sa = sav[p];
        const int   rr = rrv[p];
        float* orow = out + (size_t)b * (H_ * Q_) + p;
        #pragma unroll 4
        for (int hh = 0; hh < H_ / 2; hh++) {
            const int h = hh * 2 + sub;
            float o = fmaf(sa, S10[h], fmaf(sg, pre[h][rr], med[h]));
            __stcs(&orow[h * Q_], o);
        }
    }
}

// ---------------------------------------------------------------------------
// Inputs mapped by ELEMENT COUNT (robust to metadata ordering):
//   x: 8388608, quantiles: 811008, Wm: 65536, bm: 64, Wi: 655360, bi: 640
// Output: (B, 64, 99) f32
// ---------------------------------------------------------------------------
extern "C" void kernel_launch(void* const* d_in, const int* in_sizes, int n_in,
                              void* d_out, int out_size)
{
    const float *x = nullptr, *qu = nullptr, *Wm = nullptr,
                *bm = nullptr, *Wi = nullptr, *bi = nullptr;
    for (int i = 0; i < n_in; i++) {
        switch (in_sizes[i]) {
            case B_ * HID_:      x  = (const float*)d_in[i]; break;  // 8388608
            case B_ * Q_:        qu = (const float*)d_in[i]; break;  // 811008
            case HID_ * H_:      Wm = (const float*)d_in[i]; break;  // 65536
            case H_:             bm = (const float*)d_in[i]; break;  // 64
            case HID_ * H_ * 10: Wi = (const float*)d_in[i]; break;  // 655360
            case H_ * 10:        bi = (const float*)d_in[i]; break;  // 640
            default: break;
        }
    }
    float* out = (float*)d_out;

    cudaFuncSetAttribute(hqp_gemm, cudaFuncAttributeMaxDynamicSharedMemorySize,
                         GEMM_SMEM_BYTES);

    dim3 ggrid(NTOT / BN, B_ / BM);   // 11 x 64
    hqp_gemm<<<ggrid, 128, GEMM_SMEM_BYTES>>>(x, Wm, Wi);
    hqp_epilogue<<<B_, 256>>>(qu, bm, bi, out);
}